// round 16
// baseline (speedup 1.0000x reference)
#include <cuda_runtime.h>
#include <cuda_fp16.h>
#include <cstdint>

#define BB 8
#define SS 16384

#define SCALE_W   64.0f
#define INV_W     0.015625f
#define SCALE_M   1024.0f
#define INV_M     0.0009765625f

// ------------------------------------------------------------- device scratch
__device__ __align__(16) __half g_qTh [BB * SS * 256];   // q transposed, fp16
__device__ __align__(16) __half g_qsTh[BB * SS * 256];   // softmaxed q, fp16
__device__ __align__(16) __half g_W1h [768 * 256];       // stacked weights*64 hi
__device__ __align__(16) __half g_W1l [768 * 256];       // lo
__device__ float        g_bias1[768];
__device__ float        g_ctx [BB * 8 * 32 * 32];
__device__ float        g_rsum[BB * 256];
__device__ __align__(16) __half g_M3h [BB * 256 * 256];  // M3*1024 hi
__device__ __align__(16) __half g_M3l [BB * 256 * 256];  // lo

// ------------------------------------------------------------- smem layout
// Stage = A-pair tile (128 rows x [hi 64B | lo 64B], swizzled, 16 KB)
//       + B tile (128 rows x 64B, swizzled, 8 KB).
// 4 stages, load-before-wait, prefetch distance 2.
#define APAIR_B  16384
#define STAGE_B  24576
#define NSTAGE   4
#define SMEM_DYN 98304               // 4 stages; epilogue needs 68096 -- fits
// Epilogue (reuses same smem): S fp32 [128][132] + bias[128]
#define S_STRIDE 132
#define OFF_BIAS 67584
// k_M3 dynamic smem: sctx [256][33] + swo [32][256]
#define M3_SMEM  66560

// ------------------------------------------------------------- PTX helpers
__device__ __forceinline__ uint32_t smem_u32(const void* p) {
    uint32_t a;
    asm("{ .reg .u64 t; cvta.to.shared.u64 t, %1; cvt.u32.u64 %0, t; }"
        : "=r"(a) : "l"(p));
    return a;
}
__device__ __forceinline__ void cpa16(uint32_t s, const void* g) {
    asm volatile("cp.async.cg.shared.global [%0], [%1], 16;" :: "r"(s), "l"(g));
}
__device__ __forceinline__ void cpa_commit() {
    asm volatile("cp.async.commit_group;" ::: "memory");
}
__device__ __forceinline__ void ldsm4(uint32_t* r, uint32_t addr) {
    asm volatile("ldmatrix.sync.aligned.m8n8.x4.shared.b16 {%0,%1,%2,%3}, [%4];"
                 : "=r"(r[0]), "=r"(r[1]), "=r"(r[2]), "=r"(r[3]) : "r"(addr));
}
__device__ __forceinline__ void mma16816(float* c, const uint32_t* a,
                                         const uint32_t* b) {
    asm volatile(
        "mma.sync.aligned.m16n8k16.row.col.f32.f16.f16.f32 "
        "{%0,%1,%2,%3}, {%4,%5,%6,%7}, {%8,%9}, {%0,%1,%2,%3};"
        : "+f"(c[0]), "+f"(c[1]), "+f"(c[2]), "+f"(c[3])
        : "r"(a[0]), "r"(a[1]), "r"(a[2]), "r"(a[3]), "r"(b[0]), "r"(b[1]));
}

// ------------------------------------------------------------- prep kernels
__global__ void k_prepw(const float* __restrict__ wq, const float* __restrict__ bq,
                        const float* __restrict__ wk, const float* __restrict__ bk,
                        const float* __restrict__ wv, const float* __restrict__ bv)
{
    int r = blockIdx.x, k = threadIdx.x;
    int z = r * 256 + k;
    if (z < BB * 8 * 32 * 32) g_ctx[z] = 0.f;
    if (z < BB * 256)         g_rsum[z] = 0.f;

    const float *W, *Bp; int src;
    if (r < 256) { W = wq; Bp = bq; src = r; }
    else {
        int q2 = r - 256, p = q2 >> 7, lr = q2 & 127;
        int sub = lr >> 5, ch = lr & 31, head = 2 * p + (sub >> 1);
        W = (sub & 1) ? wv : wk;  Bp = (sub & 1) ? bv : bk;
        src = head * 32 + ch;
    }
    float v = W[src * 256 + k] * SCALE_W;
    __half h = __float2half(v);
    g_W1h[r * 256 + k] = h;
    g_W1l[r * 256 + k] = __float2half(v - __half2float(h));
    if (k == 0) g_bias1[r] = Bp[src];
}

// transpose q [b][c][s] -> qT [b][s][c], single fp16. 64c x 64s tiles.
__global__ __launch_bounds__(256) void k_prepq(const float* __restrict__ q)
{
    __shared__ float tile[64 * 68];
    int tid = threadIdx.x;
    int s0 = blockIdx.x * 64, c0 = blockIdx.y * 64, b = blockIdx.z;
    #pragma unroll
    for (int it = 0; it < 4; it++) {
        int i = tid + it * 256;
        int r = i >> 4, c4 = (i & 15) * 4;
        float4 v = *(const float4*)(q + (size_t)(b * 256 + c0 + r) * SS + s0 + c4);
        *(float4*)(tile + r * 68 + c4) = v;
    }
    __syncthreads();
    #pragma unroll
    for (int it = 0; it < 8; it++) {
        int u = tid + it * 256;
        int sl = u >> 5, cp = u & 31;
        float a = tile[(cp * 2 + 0) * 68 + sl];
        float c = tile[(cp * 2 + 1) * 68 + sl];
        __half2 hp = __halves2half2(__float2half(a), __float2half(c));
        size_t idx = ((size_t)(b * SS + s0 + sl) * 256 + c0) / 2 + cp;
        ((uint32_t*)g_qTh)[idx] = *(uint32_t*)&hp;
    }
}

// ------------------------------------------------------------- GEMM mainloop
// 128x128x256 per CTA; warp (wm,wn) owns 64x32; 2 products: Ah*B + Al*B.
__device__ __forceinline__ void load_chunk(
    uint32_t sb, int kc, int tid,
    const __half* Ah, const __half* Al, const __half* Bh)
{
    // A: 4 chunks/thread (hi|lo pairs, 128B rows, ^(row&7) swizzle)
    const int c16 = tid & 7;
    const __half* srcA = (c16 < 4 ? Ah : Al);
    const int kbA = kc * 32 + (c16 & 3) * 8;
    #pragma unroll
    for (int it = 0; it < 4; it++) {
        int row = (tid >> 3) + it * 32;
        uint32_t so = row * 128 + ((c16 ^ (row & 7)) << 4);
        cpa16(sb + so, srcA + (size_t)row * 256 + kbA);
    }
    // B: 2 chunks/thread (64B rows, ^((row>>1)&3) swizzle)
    #pragma unroll
    for (int it = 0; it < 2; it++) {
        int id = tid + it * 256;
        int row = id >> 2, c = id & 3;
        uint32_t so = row * 64 + ((c ^ ((row >> 1) & 3)) << 4);
        cpa16(sb + APAIR_B + so, Bh + (size_t)row * 256 + kc * 32 + c * 8);
    }
}

__device__ __forceinline__ void gemm128(
    char* sm, float (&acc)[4][4][4],
    const __half* Ah, const __half* Al, const __half* Bh)
{
    const int tid = threadIdx.x, w = tid >> 5, l = tid & 31;
    const int wm = w >> 2, wn = w & 3;
    uint32_t smb = smem_u32(sm);

    #pragma unroll
    for (int mi = 0; mi < 4; mi++)
        #pragma unroll
        for (int ni = 0; ni < 4; ni++)
            #pragma unroll
            for (int r = 0; r < 4; r++) acc[mi][ni][r] = 0.f;

    const int arow = wm * 64 + (l & 7) + ((l >> 3) & 1) * 8;
    const uint32_t a_off = (uint32_t)arow * 128;
    const int arsw = arow & 7, la = l >> 4;
    const int brow = wn * 32 + (l & 7) + (l >> 4) * 8;
    const uint32_t b_off = APAIR_B + (uint32_t)brow * 64;
    const int brsw = (brow >> 1) & 3, lb = (l >> 3) & 1;

    // prologue: 2 chunks in flight before first consume
    load_chunk(smb + 0 * STAGE_B, 0, tid, Ah, Al, Bh); cpa_commit();
    load_chunk(smb + 1 * STAGE_B, 1, tid, Ah, Al, Bh); cpa_commit();

    uint32_t st = smb;
    #pragma unroll 1
    for (int c = 0; c < 8; c++) {
        if (c < 6) {
            load_chunk(smb + ((c + 2) & 3) * STAGE_B, c + 2, tid, Ah, Al, Bh);
            cpa_commit();
            asm volatile("cp.async.wait_group 2;" ::: "memory");
        } else if (c == 6) {
            asm volatile("cp.async.wait_group 1;" ::: "memory");
        } else {
            asm volatile("cp.async.wait_group 0;" ::: "memory");
        }
        __syncthreads();
        #pragma unroll
        for (int ks = 0; ks < 2; ks++) {
            uint32_t bh[4][2], t4[4];
            #pragma unroll
            for (int half = 0; half < 2; half++) {
                uint32_t ba = st + b_off + half * 1024 +
                              (((ks * 2 + lb) ^ brsw) << 4);
                ldsm4(t4, ba);
                bh[2*half][0] = t4[0]; bh[2*half][1] = t4[1];
                bh[2*half+1][0] = t4[2]; bh[2*half+1][1] = t4[3];
            }
            #pragma unroll
            for (int mi = 0; mi < 4; mi++) {
                uint32_t ah[4], al4[4];
                uint32_t aa = st + a_off + mi * 2048 +
                              (((ks * 2 + la) ^ arsw) << 4);
                ldsm4(ah, aa);
                ldsm4(al4, aa ^ 64);
                #pragma unroll
                for (int ni = 0; ni < 4; ni++) {
                    mma16816(acc[mi][ni], ah,  bh[ni]);
                    mma16816(acc[mi][ni], al4, bh[ni]);
                }
            }
        }
        st += STAGE_B; if (st == smb + NSTAGE * STAGE_B) st = smb;
    }
    __syncthreads();   // protect stage smem before epilogue reuse
}

// store acc into S: transposed (S[spatial][channel]) if T, else natural.
template<bool T>
__device__ __forceinline__ void acc_to_smem(float* S, float (&acc)[4][4][4])
{
    const int tid = threadIdx.x, w = tid >> 5, l = tid & 31;
    const int wm = w >> 2, wn = w & 3;
    const int r0 = wm * 64 + (l >> 2), c0 = wn * 32 + (l & 3) * 2;
    #pragma unroll
    for (int mi = 0; mi < 4; mi++)
        #pragma unroll
        for (int ni = 0; ni < 4; ni++) {
            int r = r0 + mi * 16, cc = c0 + ni * 8;
            if (T) {
                S[cc * S_STRIDE + r]           = acc[mi][ni][0];
                S[(cc + 1) * S_STRIDE + r]     = acc[mi][ni][1];
                S[cc * S_STRIDE + r + 8]       = acc[mi][ni][2];
                S[(cc + 1) * S_STRIDE + r + 8] = acc[mi][ni][3];
            } else {
                S[r * S_STRIDE + cc]           = acc[mi][ni][0];
                S[r * S_STRIDE + cc + 1]       = acc[mi][ni][1];
                S[(r + 8) * S_STRIDE + cc]     = acc[mi][ni][2];
                S[(r + 8) * S_STRIDE + cc + 1] = acc[mi][ni][3];
            }
        }
}

// ------------------------------------------------------------- K1
__global__ void __launch_bounds__(256, 2) k1()
{
    extern __shared__ char sm[];
    const int tid = threadIdx.x;
    const int b = blockIdx.z, y = blockIdx.y, s0 = blockIdx.x * 128;

    float acc[4][4][4];
    gemm128(sm, acc,
            g_W1h + y * 128 * 256, g_W1l + y * 128 * 256,
            g_qTh + ((size_t)b * SS + s0) * 256);

    float* S = (float*)sm;                       // [128 spatial][132 channel]
    float* sbias = (float*)(sm + OFF_BIAS);
    acc_to_smem<true>(S, acc);
    if (tid < 128) sbias[tid] = g_bias1[y * 128 + tid];
    __syncthreads();

    if (y < 2) {
        // ---- q epilogue: softmax over d=32 per spatial, write qsT fp16
        const int sc = tid >> 1;
        #pragma unroll
        for (int g2 = 0; g2 < 2; g2++) {
            const int g = (tid & 1) * 2 + g2, gb = g * 32;
            float e[32], sum = 0.f;
            #pragma unroll
            for (int i = 0; i < 32; i++) {
                e[i] = __expf(S[sc * S_STRIDE + gb + i] * INV_W + sbias[gb + i]);
                sum += e[i];
            }
            float inv = __fdividef(1.f, sum);
            __half oh[32];
            #pragma unroll
            for (int i = 0; i < 32; i++) oh[i] = __float2half(e[i] * inv);
            size_t go = ((size_t)b * SS + s0 + sc) * 256 + y * 128 + gb;
            #pragma unroll
            for (int v = 0; v < 4; v++)
                *(uint4*)(g_qsTh + go + v * 8) = *(uint4*)(oh + v * 8);
        }
    } else {
        // ---- kv epilogue: in-place exp(k)+bias / v+bias, then ctx/rsum
        const int p = y - 2;
        {
            const int ch = tid & 127;
            const float bias = sbias[ch];
            const bool isk = ((ch >> 5) & 1) == 0;
            #pragma unroll 8
            for (int i = 0; i < 64; i++) {
                int sc = 2 * i + (tid >> 7);
                float v = S[sc * S_STRIDE + ch] * INV_W + bias;
                S[sc * S_STRIDE + ch] = isk ? __expf(v) : v;
            }
        }
        __syncthreads();
        const int h = tid >> 7, i0 = ((tid >> 3) & 15) * 2, j0 = (tid & 7) * 4;
        float cacc[8] = {0,0,0,0,0,0,0,0};
        float r0 = 0.f, r1 = 0.f;
        const float* E = S + h * 64 + i0;
        const float* V = S + h * 64 + 32 + j0;
        #pragma unroll 4
        for (int sc = 0; sc < 128; sc++) {
            float2 e = *(const float2*)(E + sc * S_STRIDE);
            float4 v = *(const float4*)(V + sc * S_STRIDE);
            r0 += e.x; r1 += e.y;
            cacc[0] += e.x * v.x; cacc[1] += e.x * v.y;
            cacc[2] += e.x * v.z; cacc[3] += e.x * v.w;
            cacc[4] += e.y * v.x; cacc[5] += e.y * v.y;
            cacc[6] += e.y * v.z; cacc[7] += e.y * v.w;
        }
        int gh = b * 8 + p * 2 + h;
        float* c0 = &g_ctx[(gh * 32 + i0) * 32 + j0];
        atomicAdd(c0 + 0, cacc[0]); atomicAdd(c0 + 1, cacc[1]);
        atomicAdd(c0 + 2, cacc[2]); atomicAdd(c0 + 3, cacc[3]);
        atomicAdd(c0 + 32, cacc[4]); atomicAdd(c0 + 33, cacc[5]);
        atomicAdd(c0 + 34, cacc[6]); atomicAdd(c0 + 35, cacc[7]);
        if (j0 == 0) {
            atomicAdd(&g_rsum[gh * 32 + i0], r0);
            atomicAdd(&g_rsum[gh * 32 + i0 + 1], r1);
        }
    }
}

// ------------------------------------------------------------- k_M3
__global__ __launch_bounds__(256) void k_M3(const float* __restrict__ wo)
{
    extern __shared__ float dsm[];
    float* sctx = dsm;               // [256][33]
    float* swo  = dsm + 256 * 33;    // [32][256]
    const int b = blockIdx.x, ot = blockIdx.y, tid = threadIdx.x;

    for (int idx = tid; idx < 8192; idx += 256) {
        sctx[(idx >> 5) * 33 + (idx & 31)] = g_ctx[b * 8192 + idx];
        swo[idx] = wo[(size_t)(ot * 32) * 256 + idx];
    }
    const float inv = 0.17677669529663687f * SCALE_M / g_rsum[b * 256 + tid];
    __syncthreads();

    float creg[32];
    #pragma unroll
    for (int j = 0; j < 32; j++) creg[j] = sctx[tid * 33 + j];
    const float* swn = swo + (tid >> 5) * 32;

    #pragma unroll 4
    for (int oo = 0; oo < 32; oo++) {
        float s = 0.f;
        #pragma unroll
        for (int j = 0; j < 32; j++) s += swn[oo * 256 + j] * creg[j];
        float m = s * inv;
        __half h = __float2half(m);
        size_t o = (size_t)(b * 256 + ot * 32 + oo) * 256 + tid;
        g_M3h[o] = h;
        g_M3l[o] = __float2half(m - __half2float(h));
    }
}

// ------------------------------------------------------------- K3
__global__ void __launch_bounds__(256, 2) k3(const float* __restrict__ bo,
                                             float* __restrict__ outp)
{
    extern __shared__ char sm[];
    const int tid = threadIdx.x;
    const int b = blockIdx.z, y = blockIdx.y, s0 = blockIdx.x * 128;

    float acc[4][4][4];
    gemm128(sm, acc,
            g_M3h + (size_t)(b * 256 + y * 128) * 256,
            g_M3l + (size_t)(b * 256 + y * 128) * 256,
            g_qsTh + ((size_t)b * SS + s0) * 256);

    float* S = (float*)sm;                       // [128 row][132 spatial]
    float* sbias = (float*)(sm + OFF_BIAS);
    acc_to_smem<false>(S, acc);
    if (tid < 128) sbias[tid] = bo[y * 128 + tid];
    __syncthreads();

    #pragma unroll 4
    for (int i2 = tid; i2 < 128 * 32; i2 += 256) {
        int rr = i2 >> 5, c4 = (i2 & 31) * 4;
        float4 v = *(float4*)(S + rr * S_STRIDE + c4);
        float bb2 = sbias[rr];
        v.x = v.x * INV_M + bb2; v.y = v.y * INV_M + bb2;
        v.z = v.z * INV_M + bb2; v.w = v.w * INV_M + bb2;
        *(float4*)(outp + (size_t)(b * 256 + y * 128 + rr) * SS + s0 + c4) = v;
    }
}

// ---------------------------------------------------------------------------
extern "C" void kernel_launch(void* const* d_in, const int* in_sizes, int n_in,
                              void* d_out, int out_size)
{
    const float* q  = (const float*)d_in[0];
    const float* wq = (const float*)d_in[1];
    const float* bq = (const float*)d_in[2];
    const float* wk = (const float*)d_in[3];
    const float* bk = (const float*)d_in[4];
    const float* wv = (const float*)d_in[5];
    const float* bv = (const float*)d_in[6];
    const float* wo = (const float*)d_in[7];
    const float* bo = (const float*)d_in[8];
    float* out = (float*)d_out;

    static int once = 0;
    if (!once) {
        cudaFuncSetAttribute(k1, cudaFuncAttributeMaxDynamicSharedMemorySize, SMEM_DYN);
        cudaFuncSetAttribute(k3, cudaFuncAttributeMaxDynamicSharedMemorySize, SMEM_DYN);
        cudaFuncSetAttribute(k_M3, cudaFuncAttributeMaxDynamicSharedMemorySize, M3_SMEM);
        once = 1;
    }

    k_prepw<<<768, 256>>>(wq, bq, wk, bk, wv, bv);
    k_prepq<<<dim3(SS / 64, 4, BB), 256>>>(q);
    k1<<<dim3(SS / 128, 6, BB), 256, SMEM_DYN>>>();
    k_M3<<<dim3(BB, 8), 256, M3_SMEM>>>(wo);
    k3<<<dim3(SS / 128, 2, BB), 256, SMEM_DYN>>>(bo, out);
}

// round 17
// speedup vs baseline: 1.2588x; 1.2588x over previous
#include <cuda_runtime.h>
#include <cuda_fp16.h>
#include <cstdint>

#define BB 8
#define SS 16384

#define SCALE_W   64.0f
#define INV_W     0.015625f
#define SCALE_M   1024.0f
#define INV_M     0.0009765625f

// ------------------------------------------------------------- device scratch
__device__ __align__(16) __half g_qTh [BB * SS * 256];   // q transposed, fp16
__device__ __align__(16) __half g_qsTh[BB * SS * 256];   // softmaxed q, fp16
__device__ __align__(16) __half g_W1h [768 * 256];       // stacked weights*64
__device__ float        g_bias1[768];
__device__ float        g_ctx [BB * 8 * 32 * 32];
__device__ float        g_rsum[BB * 256];
__device__ __align__(16) __half g_M3h [BB * 256 * 256];  // M3*1024

// ------------------------------------------------------------- smem layout
// Stage = A tile (128 rows x 64B, swizzled, 8 KB) + B tile (same, 8 KB).
// 3 stages, load-before-wait (R14 proven shape).
#define ATILE_B  8192
#define STAGE_B  16384
#define NSTAGE   3
#define SMEM_DYN 68096               // epilogue S[128][132]+bias dominates
// Epilogue (reuses same smem): S fp32 [128][132] + bias[128]
#define S_STRIDE 132
#define OFF_BIAS 67584
// k_M3 dynamic smem: sctx [256][33] + swo [32][256]
#define M3_SMEM  66560

// ------------------------------------------------------------- PTX helpers
__device__ __forceinline__ uint32_t smem_u32(const void* p) {
    uint32_t a;
    asm("{ .reg .u64 t; cvta.to.shared.u64 t, %1; cvt.u32.u64 %0, t; }"
        : "=r"(a) : "l"(p));
    return a;
}
__device__ __forceinline__ void cpa16(uint32_t s, const void* g) {
    asm volatile("cp.async.cg.shared.global [%0], [%1], 16;" :: "r"(s), "l"(g));
}
__device__ __forceinline__ void cpa_commit() {
    asm volatile("cp.async.commit_group;" ::: "memory");
}
__device__ __forceinline__ void ldsm4(uint32_t* r, uint32_t addr) {
    asm volatile("ldmatrix.sync.aligned.m8n8.x4.shared.b16 {%0,%1,%2,%3}, [%4];"
                 : "=r"(r[0]), "=r"(r[1]), "=r"(r[2]), "=r"(r[3]) : "r"(addr));
}
__device__ __forceinline__ void mma16816(float* c, const uint32_t* a,
                                         const uint32_t* b) {
    asm volatile(
        "mma.sync.aligned.m16n8k16.row.col.f32.f16.f16.f32 "
        "{%0,%1,%2,%3}, {%4,%5,%6,%7}, {%8,%9}, {%0,%1,%2,%3};"
        : "+f"(c[0]), "+f"(c[1]), "+f"(c[2]), "+f"(c[3])
        : "r"(a[0]), "r"(a[1]), "r"(a[2]), "r"(a[3]), "r"(b[0]), "r"(b[1]));
}

// ------------------------------------------------------------- prep kernels
__global__ void k_prepw(const float* __restrict__ wq, const float* __restrict__ bq,
                        const float* __restrict__ wk, const float* __restrict__ bk,
                        const float* __restrict__ wv, const float* __restrict__ bv)
{
    int r = blockIdx.x, k = threadIdx.x;
    int z = r * 256 + k;
    if (z < BB * 8 * 32 * 32) g_ctx[z] = 0.f;
    if (z < BB * 256)         g_rsum[z] = 0.f;

    const float *W, *Bp; int src;
    if (r < 256) { W = wq; Bp = bq; src = r; }
    else {
        int q2 = r - 256, p = q2 >> 7, lr = q2 & 127;
        int sub = lr >> 5, ch = lr & 31, head = 2 * p + (sub >> 1);
        W = (sub & 1) ? wv : wk;  Bp = (sub & 1) ? bv : bk;
        src = head * 32 + ch;
    }
    g_W1h[r * 256 + k] = __float2half(W[src * 256 + k] * SCALE_W);
    if (k == 0) g_bias1[r] = Bp[src];
}

// transpose q [b][c][s] -> qT [b][s][c], single fp16. 64c x 64s tiles.
__global__ __launch_bounds__(256) void k_prepq(const float* __restrict__ q)
{
    __shared__ float tile[64 * 68];
    int tid = threadIdx.x;
    int s0 = blockIdx.x * 64, c0 = blockIdx.y * 64, b = blockIdx.z;
    #pragma unroll
    for (int it = 0; it < 4; it++) {
        int i = tid + it * 256;
        int r = i >> 4, c4 = (i & 15) * 4;
        float4 v = *(const float4*)(q + (size_t)(b * 256 + c0 + r) * SS + s0 + c4);
        *(float4*)(tile + r * 68 + c4) = v;
    }
    __syncthreads();
    #pragma unroll
    for (int it = 0; it < 8; it++) {
        int u = tid + it * 256;
        int sl = u >> 5, cp = u & 31;
        float a = tile[(cp * 2 + 0) * 68 + sl];
        float c = tile[(cp * 2 + 1) * 68 + sl];
        __half2 hp = __halves2half2(__float2half(a), __float2half(c));
        size_t idx = ((size_t)(b * SS + s0 + sl) * 256 + c0) / 2 + cp;
        ((uint32_t*)g_qTh)[idx] = *(uint32_t*)&hp;
    }
}

// ------------------------------------------------------------- GEMM mainloop
// 128x128x256 per CTA; warp (wm,wn) owns 64x32; single fp16 product.
__device__ __forceinline__ void load_chunk(
    uint32_t sb, int kc, int tid,
    const __half* Ah, const __half* Bh)
{
    #pragma unroll
    for (int it = 0; it < 2; it++) {
        int id = tid + it * 256;             // 0..511: 128 rows x 4 16B cols
        int row = id >> 2, c = id & 3;
        uint32_t so = row * 64 + ((c ^ ((row >> 1) & 3)) << 4);
        size_t go = (size_t)row * 256 + kc * 32 + c * 8;
        cpa16(sb + so,           Ah + go);
        cpa16(sb + ATILE_B + so, Bh + go);
    }
}

__device__ __forceinline__ void gemm128(
    char* sm, float (&acc)[4][4][4],
    const __half* Ah, const __half* Bh)
{
    const int tid = threadIdx.x, w = tid >> 5, l = tid & 31;
    const int wm = w >> 2, wn = w & 3;
    uint32_t smb = smem_u32(sm);

    #pragma unroll
    for (int mi = 0; mi < 4; mi++)
        #pragma unroll
        for (int ni = 0; ni < 4; ni++)
            #pragma unroll
            for (int r = 0; r < 4; r++) acc[mi][ni][r] = 0.f;

    const int arow = wm * 64 + (l & 7) + ((l >> 3) & 1) * 8;
    const uint32_t a_off = (uint32_t)arow * 64;
    const int arsw = (arow >> 1) & 3, la = l >> 4;
    const int brow = wn * 32 + (l & 7) + (l >> 4) * 8;
    const uint32_t b_off = ATILE_B + (uint32_t)brow * 64;
    const int brsw = (brow >> 1) & 3, lb = (l >> 3) & 1;

    load_chunk(smb, 0, tid, Ah, Bh);
    cpa_commit();

    uint32_t st = smb, ld = smb + STAGE_B;
    #pragma unroll 1
    for (int c = 0; c < 8; c++) {
        if (c < 7) {
            load_chunk(ld, c + 1, tid, Ah, Bh);
            cpa_commit();
            ld += STAGE_B; if (ld == smb + NSTAGE * STAGE_B) ld = smb;
            asm volatile("cp.async.wait_group 1;" ::: "memory");
        } else {
            asm volatile("cp.async.wait_group 0;" ::: "memory");
        }
        __syncthreads();
        #pragma unroll
        for (int ks = 0; ks < 2; ks++) {
            uint32_t bh[4][2], t4[4];
            #pragma unroll
            for (int half = 0; half < 2; half++) {
                uint32_t ba = st + b_off + half * 1024 +
                              (((ks * 2 + lb) ^ brsw) << 4);
                ldsm4(t4, ba);
                bh[2*half][0] = t4[0]; bh[2*half][1] = t4[1];
                bh[2*half+1][0] = t4[2]; bh[2*half+1][1] = t4[3];
            }
            #pragma unroll
            for (int mi = 0; mi < 4; mi++) {
                uint32_t ah[4];
                uint32_t aa = st + a_off + mi * 1024 +
                              (((ks * 2 + la) ^ arsw) << 4);
                ldsm4(ah, aa);
                #pragma unroll
                for (int ni = 0; ni < 4; ni++)
                    mma16816(acc[mi][ni], ah, bh[ni]);
            }
        }
        st += STAGE_B; if (st == smb + NSTAGE * STAGE_B) st = smb;
    }
    __syncthreads();   // protect stage smem before epilogue reuse
}

// store acc into S: transposed (S[spatial][channel]) if T, else natural.
template<bool T>
__device__ __forceinline__ void acc_to_smem(float* S, float (&acc)[4][4][4])
{
    const int tid = threadIdx.x, w = tid >> 5, l = tid & 31;
    const int wm = w >> 2, wn = w & 3;
    const int r0 = wm * 64 + (l >> 2), c0 = wn * 32 + (l & 3) * 2;
    #pragma unroll
    for (int mi = 0; mi < 4; mi++)
        #pragma unroll
        for (int ni = 0; ni < 4; ni++) {
            int r = r0 + mi * 16, cc = c0 + ni * 8;
            if (T) {
                S[cc * S_STRIDE + r]           = acc[mi][ni][0];
                S[(cc + 1) * S_STRIDE + r]     = acc[mi][ni][1];
                S[cc * S_STRIDE + r + 8]       = acc[mi][ni][2];
                S[(cc + 1) * S_STRIDE + r + 8] = acc[mi][ni][3];
            } else {
                S[r * S_STRIDE + cc]           = acc[mi][ni][0];
                S[r * S_STRIDE + cc + 1]       = acc[mi][ni][1];
                S[(r + 8) * S_STRIDE + cc]     = acc[mi][ni][2];
                S[(r + 8) * S_STRIDE + cc + 1] = acc[mi][ni][3];
            }
        }
}

// ------------------------------------------------------------- K1
__global__ void __launch_bounds__(256, 2) k1()
{
    extern __shared__ char sm[];
    const int tid = threadIdx.x;
    const int b = blockIdx.z, y = blockIdx.y, s0 = blockIdx.x * 128;

    float acc[4][4][4];
    gemm128(sm, acc,
            g_W1h + y * 128 * 256,
            g_qTh + ((size_t)b * SS + s0) * 256);

    float* S = (float*)sm;                       // [128 spatial][132 channel]
    float* sbias = (float*)(sm + OFF_BIAS);
    acc_to_smem<true>(S, acc);
    if (tid < 128) sbias[tid] = g_bias1[y * 128 + tid];
    __syncthreads();

    if (y < 2) {
        // ---- q epilogue: softmax over d=32 per spatial, write qsT fp16
        const int sc = tid >> 1;
        #pragma unroll
        for (int g2 = 0; g2 < 2; g2++) {
            const int g = (tid & 1) * 2 + g2, gb = g * 32;
            float e[32], sum = 0.f;
            #pragma unroll
            for (int i = 0; i < 32; i++) {
                e[i] = __expf(S[sc * S_STRIDE + gb + i] * INV_W + sbias[gb + i]);
                sum += e[i];
            }
            float inv = __fdividef(1.f, sum);
            __half oh[32];
            #pragma unroll
            for (int i = 0; i < 32; i++) oh[i] = __float2half(e[i] * inv);
            size_t go = ((size_t)b * SS + s0 + sc) * 256 + y * 128 + gb;
            #pragma unroll
            for (int v = 0; v < 4; v++)
                *(uint4*)(g_qsTh + go + v * 8) = *(uint4*)(oh + v * 8);
        }
    } else {
        // ---- kv epilogue: in-place exp(k)+bias / v+bias, then ctx/rsum
        const int p = y - 2;
        {
            const int ch = tid & 127;
            const float bias = sbias[ch];
            const bool isk = ((ch >> 5) & 1) == 0;
            #pragma unroll 8
            for (int i = 0; i < 64; i++) {
                int sc = 2 * i + (tid >> 7);
                float v = S[sc * S_STRIDE + ch] * INV_W + bias;
                S[sc * S_STRIDE + ch] = isk ? __expf(v) : v;
            }
        }
        __syncthreads();
        const int h = tid >> 7, i0 = ((tid >> 3) & 15) * 2, j0 = (tid & 7) * 4;
        float cacc[8] = {0,0,0,0,0,0,0,0};
        float r0 = 0.f, r1 = 0.f;
        const float* E = S + h * 64 + i0;
        const float* V = S + h * 64 + 32 + j0;
        #pragma unroll 4
        for (int sc = 0; sc < 128; sc++) {
            float2 e = *(const float2*)(E + sc * S_STRIDE);
            float4 v = *(const float4*)(V + sc * S_STRIDE);
            r0 += e.x; r1 += e.y;
            cacc[0] += e.x * v.x; cacc[1] += e.x * v.y;
            cacc[2] += e.x * v.z; cacc[3] += e.x * v.w;
            cacc[4] += e.y * v.x; cacc[5] += e.y * v.y;
            cacc[6] += e.y * v.z; cacc[7] += e.y * v.w;
        }
        int gh = b * 8 + p * 2 + h;
        float* c0 = &g_ctx[(gh * 32 + i0) * 32 + j0];
        atomicAdd(c0 + 0, cacc[0]); atomicAdd(c0 + 1, cacc[1]);
        atomicAdd(c0 + 2, cacc[2]); atomicAdd(c0 + 3, cacc[3]);
        atomicAdd(c0 + 32, cacc[4]); atomicAdd(c0 + 33, cacc[5]);
        atomicAdd(c0 + 34, cacc[6]); atomicAdd(c0 + 35, cacc[7]);
        if (j0 == 0) {
            atomicAdd(&g_rsum[gh * 32 + i0], r0);
            atomicAdd(&g_rsum[gh * 32 + i0 + 1], r1);
        }
    }
}

// ------------------------------------------------------------- k_M3
__global__ __launch_bounds__(256) void k_M3(const float* __restrict__ wo)
{
    extern __shared__ float dsm[];
    float* sctx = dsm;               // [256][33]
    float* swo  = dsm + 256 * 33;    // [32][256]
    const int b = blockIdx.x, ot = blockIdx.y, tid = threadIdx.x;

    for (int idx = tid; idx < 8192; idx += 256) {
        sctx[(idx >> 5) * 33 + (idx & 31)] = g_ctx[b * 8192 + idx];
        swo[idx] = wo[(size_t)(ot * 32) * 256 + idx];
    }
    const float inv = 0.17677669529663687f * SCALE_M / g_rsum[b * 256 + tid];
    __syncthreads();

    float creg[32];
    #pragma unroll
    for (int j = 0; j < 32; j++) creg[j] = sctx[tid * 33 + j];
    const float* swn = swo + (tid >> 5) * 32;

    #pragma unroll 4
    for (int oo = 0; oo < 32; oo++) {
        float s = 0.f;
        #pragma unroll
        for (int j = 0; j < 32; j++) s += swn[oo * 256 + j] * creg[j];
        g_M3h[(size_t)(b * 256 + ot * 32 + oo) * 256 + tid] =
            __float2half(s * inv);
    }
}

// ------------------------------------------------------------- K3
__global__ void __launch_bounds__(256, 2) k3(const float* __restrict__ bo,
                                             float* __restrict__ outp)
{
    extern __shared__ char sm[];
    const int tid = threadIdx.x;
    const int b = blockIdx.z, y = blockIdx.y, s0 = blockIdx.x * 128;

    float acc[4][4][4];
    gemm128(sm, acc,
            g_M3h + (size_t)(b * 256 + y * 128) * 256,
            g_qsTh + ((size_t)b * SS + s0) * 256);

    float* S = (float*)sm;                       // [128 row][132 spatial]
    float* sbias = (float*)(sm + OFF_BIAS);
    acc_to_smem<false>(S, acc);
    if (tid < 128) sbias[tid] = bo[y * 128 + tid];
    __syncthreads();

    #pragma unroll 4
    for (int i2 = tid; i2 < 128 * 32; i2 += 256) {
        int rr = i2 >> 5, c4 = (i2 & 31) * 4;
        float4 v = *(float4*)(S + rr * S_STRIDE + c4);
        float bb2 = sbias[rr];
        v.x = v.x * INV_M + bb2; v.y = v.y * INV_M + bb2;
        v.z = v.z * INV_M + bb2; v.w = v.w * INV_M + bb2;
        *(float4*)(outp + (size_t)(b * 256 + y * 128 + rr) * SS + s0 + c4) = v;
    }
}

// ---------------------------------------------------------------------------
extern "C" void kernel_launch(void* const* d_in, const int* in_sizes, int n_in,
                              void* d_out, int out_size)
{
    const float* q  = (const float*)d_in[0];
    const float* wq = (const float*)d_in[1];
    const float* bq = (const float*)d_in[2];
    const float* wk = (const float*)d_in[3];
    const float* bk = (const float*)d_in[4];
    const float* wv = (const float*)d_in[5];
    const float* bv = (const float*)d_in[6];
    const float* wo = (const float*)d_in[7];
    const float* bo = (const float*)d_in[8];
    float* out = (float*)d_out;

    static int once = 0;
    if (!once) {
        cudaFuncSetAttribute(k1, cudaFuncAttributeMaxDynamicSharedMemorySize, SMEM_DYN);
        cudaFuncSetAttribute(k3, cudaFuncAttributeMaxDynamicSharedMemorySize, SMEM_DYN);
        cudaFuncSetAttribute(k_M3, cudaFuncAttributeMaxDynamicSharedMemorySize, M3_SMEM);
        once = 1;
    }

    k_prepw<<<768, 256>>>(wq, bq, wk, bk, wv, bv);
    k_prepq<<<dim3(SS / 64, 4, BB), 256>>>(q);
    k1<<<dim3(SS / 128, 6, BB), 256, SMEM_DYN>>>();
    k_M3<<<dim3(BB, 8), 256, M3_SMEM>>>(wo);
    k3<<<dim3(SS / 128, 2, BB), 256, SMEM_DYN>>>(bo, out);
}